// round 7
// baseline (speedup 1.0000x reference)
#include <cuda_runtime.h>
#include <math.h>

// ReacPartialGbModel: B=4096 RK4 integrations, T=256 steps.
// r1(x0), r2(x1) -> cubic-Hermite LUTs (ODE affine terms folded in).
// r3 software-pipelined (k1-stage r3 of step t+1 computed during step t;
// S1_{t+1}=S4_t). NEW: each warp integrates TWO batch elements (A,B) with
// shared weights; the two independent chains interleave through all stalls.
// Single merged build kernel (2 launches/call -> ncu -s 5 hits main kernel).

namespace {

constexpr int kT = 256;
constexpr int kB = 4096;
constexpr int kN = 8192;
constexpr float kLo   = -64.0f;
constexpr float kH    = 128.0f / kN;   // 1/64
constexpr float kInvH = kN / 128.0f;   // 64
constexpr float kSc   = 2.885390081777927f;  // 2*log2(e)

__device__ __align__(16) float4 g_lutX[2 * kN];   // [2i]=A, [2i+1]=R
__device__ __align__(16) float4 g_lutY[kN];       // B

typedef unsigned long long ull;

// ---------------- helpers ---------------------------------------------------
__device__ __forceinline__ float tanh_acc(float x) {   // build-time, ~1e-7
    float ax = fabsf(x);
    float e  = __expf(-2.0f * ax);
    float r  = __fdividef(1.0f - e, 1.0f + e);
    return copysignf(r, x);
}
__device__ __forceinline__ float tanh_pre(float a) {   // input prescaled 2*log2e
    float e; asm("ex2.approx.f32 %0, %1;" : "=f"(e) : "f"(a));
    float s = e + 1.0f;
    float r; asm("rcp.approx.f32 %0, %1;" : "=f"(r) : "f"(s));
    return fmaf(-2.0f, r, 1.0f);
}
__device__ __forceinline__ ull fma2(ull a, ull b, ull c) {
    ull d; asm("fma.rn.f32x2 %0, %1, %2, %3;" : "=l"(d) : "l"(a), "l"(b), "l"(c));
    return d;
}
__device__ __forceinline__ ull add2(ull a, ull b) {
    ull d; asm("add.rn.f32x2 %0, %1, %2;" : "=l"(d) : "l"(a), "l"(b));
    return d;
}
__device__ __forceinline__ ull pk(float lo, float hi) {
    ull d; asm("mov.b64 %0, {%1, %2};" : "=l"(d) : "f"(lo), "f"(hi));
    return d;
}
__device__ __forceinline__ float upadd(ull v) {
    float lo, hi; asm("mov.b64 {%0, %1}, %2;" : "=f"(lo), "=f"(hi) : "l"(v));
    return lo + hi;
}
__device__ __forceinline__ float bfly(float v) {
#pragma unroll
    for (int m = 16; m > 0; m >>= 1) v += __shfl_xor_sync(0xffffffffu, v, m);
    return v;
}

// ---------------- merged build kernel ---------------------------------------
// thread (net, i) evaluates nodes i and i+1 of net's MLP and writes the
// Hermite cubic coefficients for interval i directly.
__device__ void eval_raw(float x,
                         const float* __restrict__ w0, const float* __restrict__ b0,
                         const float* __restrict__ w1, const float* __restrict__ b1,
                         const float* __restrict__ w2, const float* __restrict__ b2,
                         float& y_out, float& d_out)
{
    float t0[32], s0[32];
#pragma unroll
    for (int i = 0; i < 32; ++i) {
        float a  = fmaf(w0[i], x, b0[i]);
        float th = tanh_acc(a);
        t0[i] = th;
        s0[i] = (1.0f - th * th) * w0[i];
    }
    float y = b2[0], d = 0.0f;
    for (int j = 0; j < 32; ++j) {
        float a = b1[j], da = 0.0f;
#pragma unroll
        for (int i = 0; i < 32; ++i) {
            float w = w1[i * 32 + j];
            a  = fmaf(t0[i], w, a);
            da = fmaf(s0[i], w, da);
        }
        float th = tanh_acc(a);
        y = fmaf(w2[j], th, y);
        d = fmaf(w2[j] * (1.0f - th * th), da, d);
    }
    y_out = y; d_out = d;
}

__device__ __forceinline__ float4 hermite(float y0, float d0, float y1, float d1) {
    float hd0 = kH * d0, hd1 = kH * d1;
    float dy  = y1 - y0;
    return make_float4(y0, hd0,
                       3.0f * dy - 2.0f * hd0 - hd1,
                       -2.0f * dy + hd0 + hd1);
}

__global__ void build_all(const float* __restrict__ W0, const float* __restrict__ B0,
                          const float* __restrict__ W1, const float* __restrict__ B1,
                          const float* __restrict__ W2, const float* __restrict__ B2,
                          const float* __restrict__ V0, const float* __restrict__ C0,
                          const float* __restrict__ V1, const float* __restrict__ C1,
                          const float* __restrict__ V2, const float* __restrict__ C2)
{
    int idx = blockIdx.x * blockDim.x + threadIdx.x;
    if (idx >= 2 * kN) return;
    int net = idx / kN;
    int i   = idx - net * kN;
    float xa = kLo + i * kH;
    float xb = xa + kH;
    float y0, d0, y1, d1;
    if (net == 0) {
        eval_raw(xa, W0, B0, W1, B1, W2, B2, y0, d0);
        eval_raw(xb, W0, B0, W1, B1, W2, B2, y1, d1);
        // r1 = 0.3*y.  A = (0.1*Ca + r1)/0.3, Ca = 0.3x+0.5 ; R = r1*5
        float A0 = (0.1f * fmaf(0.3f, xa, 0.5f) + 0.3f * y0) * (1.0f / 0.3f);
        float A1 = (0.1f * fmaf(0.3f, xb, 0.5f) + 0.3f * y1) * (1.0f / 0.3f);
        float Ad0 = (0.03f + 0.3f * d0) * (1.0f / 0.3f);
        float Ad1 = (0.03f + 0.3f * d1) * (1.0f / 0.3f);
        g_lutX[2 * i]     = hermite(A0, Ad0, A1, Ad1);
        g_lutX[2 * i + 1] = hermite(1.5f * y0, 1.5f * d0, 1.5f * y1, 1.5f * d1);
    } else {
        eval_raw(xa, V0, C0, V1, C1, V2, C2, y0, d0);
        eval_raw(xb, V0, C0, V1, C1, V2, C2, y1, d1);
        // r2 = 0.2*y.  B = (0.1*Cb + 3*r2)*5, Cb = 0.2x+0.5
        float Bv0 = (0.1f * fmaf(0.2f, xa, 0.5f) + 0.6f * y0) * 5.0f;
        float Bv1 = (0.1f * fmaf(0.2f, xb, 0.5f) + 0.6f * y1) * 5.0f;
        float Bd0 = (0.02f + 0.6f * d0) * 5.0f;
        float Bd1 = (0.02f + 0.6f * d1) * 5.0f;
        g_lutY[i] = hermite(Bv0, Bd0, Bv1, Bd1);
    }
}

// ---------------- main kernel ------------------------------------------------
struct Elem {
    float x0, x1;
    ull   xq[8];
    float up[8];
    ull   S4p;
    float S1s, Uc, r3s1;
    // per-step carried temps
    float u, cafs, S4s, Un;
    ull   px;
    float q2, q3, q1;
    float r3s23, r3s4, r3s1n;
};

__global__ void __launch_bounds__(128, 2)
rk4_kernel(const float* __restrict__ useq, const float* __restrict__ xz0,
           const float* __restrict__ r3W0, const float* __restrict__ r3b0,
           const float* __restrict__ r3W1, const float* __restrict__ r3b1,
           const float* __restrict__ r3W2, const float* __restrict__ r3b2,
           float* __restrict__ out)
{
    const int wslot = threadIdx.x >> 5;
    const int wid   = blockIdx.x * 4 + wslot;   // warp id; handles 2 elements
    const int lane  = threadIdx.x & 31;

    // per warp: A: 2x96 parity, B: 2x96 parity, qA: 32, qB: 32  = 448 floats
    __shared__ __align__(16) float sbuf[4][448];
    float* bufA0  = sbuf[wslot];
    float* bufB0  = sbuf[wslot] + 192;
    float* qbufA  = sbuf[wslot] + 384;
    float* qbufB  = sbuf[wslot] + 416;

    // ---- shared p3 weights, prescaled by 2*log2e, packed pairs -------------
    ull w30p[8], w31p[16];
    float wu[8];
#pragma unroll
    for (int j = 0; j < 8; ++j)
        w30p[j] = pk(r3W0[(2 * j) * 32 + lane] * kSc,
                     r3W0[(2 * j + 1) * 32 + lane] * kSc);
#pragma unroll
    for (int k = 0; k < 8; ++k) wu[k] = r3W0[(16 + k) * 32 + lane] * kSc;
#pragma unroll
    for (int j = 0; j < 16; ++j)
        w31p[j] = pk(r3W1[(2 * j) * 32 + lane] * kSc,
                     r3W1[(2 * j + 1) * 32 + lane] * kSc);
    const float b30s = r3b0[lane] * kSc;
    const ull   b31p = pk(r3b1[lane] * kSc, 0.0f);
    const float w32  = r3W2[lane], b32 = r3b2[0];

    const float4* lutX = g_lutX;
    const float4* lutY = g_lutY;

    // ---- load state for both elements --------------------------------------
    Elem A, B;
    {
        const float* xza = xz0 + (2 * wid) * 26;
        const float* xzb = xz0 + (2 * wid + 1) * 26;
        A.x0 = xza[0]; A.x1 = xza[1];
        B.x0 = xzb[0]; B.x1 = xzb[1];
#pragma unroll
        for (int j = 0; j < 8; ++j) {
            A.xq[j] = pk(xza[2 + 2 * j], xza[3 + 2 * j]);
            B.xq[j] = pk(xzb[2 + 2 * j], xzb[3 + 2 * j]);
        }
#pragma unroll
        for (int k = 0; k < 8; ++k) {
            A.up[k] = xza[18 + k];
            B.up[k] = xzb[18 + k];
        }
    }

    const float4* uptrA = reinterpret_cast<const float4*>(useq + (2 * wid) * kT);
    const float4* uptrB = reinterpret_cast<const float4*>(useq + (2 * wid + 1) * kT);
    float2* outA = reinterpret_cast<float2*>(out) + (2 * wid) * kT;
    float2* outB = reinterpret_cast<float2*>(out) + (2 * wid + 1) * kT;

    auto kof = [&](float xa0, float xa1, float r3s, float cafs,
                   float& k0, float& k1v) {
        float xf0 = fmaf(xa0, kInvH, (float)(kN / 2));
        float f0  = fminf(fmaxf(floorf(xf0), 0.0f), (float)(kN - 1));
        float t0  = xf0 - f0;
        int   i0  = (int)f0;
        float4 cA = __ldg(&lutX[2 * i0]);
        float4 cR = __ldg(&lutX[2 * i0 + 1]);
        float xf1 = fmaf(xa1, kInvH, (float)(kN / 2));
        float f1  = fminf(fmaxf(floorf(xf1), 0.0f), (float)(kN - 1));
        float t1  = xf1 - f1;
        int   i1  = (int)f1;
        float4 cB = __ldg(&lutY[i1]);
        float Av  = fmaf(fmaf(fmaf(cA.w, t0, cA.z), t0, cA.y), t0, cA.x);
        float Rv  = fmaf(fmaf(fmaf(cR.w, t0, cR.z), t0, cR.y), t0, cR.x);
        float Bv  = fmaf(fmaf(fmaf(cB.w, t1, cB.z), t1, cB.y), t1, cB.x);
        k0  = cafs - Av;
        k1v = Rv - Bv + r3s;
    };

    // ---- phase functions -----------------------------------------------------
    auto phaseA = [&](Elem& E, int p, float u, float* buf) {
        E.u    = u;
        E.cafs = fmaf(u, 0.5f / 3.0f, 1.0f / 3.0f);
        E.px   = pk(E.x0, E.x1);
        E.S4s  = upadd(fma2(E.px, w30p[7], E.S4p));
        float a3_23 = fmaf(0.5f, E.S1s + E.S4s, E.Uc);
        float a3_4  = E.S4s + E.Uc;
        float Una = b30s, Unb = 0.0f;
#pragma unroll
        for (int k = 0; k < 6; k += 2) {
            Una = fmaf(E.up[(p + 1 + k) & 7], wu[k],     Una);
            Unb = fmaf(E.up[(p + 2 + k) & 7], wu[k + 1], Unb);
        }
        Una = fmaf(E.up[(p + 7) & 7], wu[6], Una);
        Unb = fmaf(u, wu[7], Unb);
        E.Un = Una + Unb;
        float a3_1n = E.S4s + E.Un;
        buf[lane]      = tanh_pre(a3_23);
        buf[32 + lane] = tanh_pre(a3_4);
        buf[64 + lane] = tanh_pre(a3_1n);
    };

    auto phaseB = [&](Elem& E, const float* buf, float* qslot) {
        ull C2a = b31p, C2b = 0ull, C3a = b31p, C3b = 0ull,
            C1a = b31p, C1b = 0ull;
        const ulonglong2* bq = reinterpret_cast<const ulonglong2*>(buf);
#pragma unroll
        for (int q = 0; q < 8; ++q) {
            ulonglong2 v2 = bq[q];
            C2a = fma2(v2.x, w31p[2 * q],     C2a);
            C2b = fma2(v2.y, w31p[2 * q + 1], C2b);
            ulonglong2 v3 = bq[8 + q];
            C3a = fma2(v3.x, w31p[2 * q],     C3a);
            C3b = fma2(v3.y, w31p[2 * q + 1], C3b);
            ulonglong2 v1 = bq[16 + q];
            C1a = fma2(v1.x, w31p[2 * q],     C1a);
            C1b = fma2(v1.y, w31p[2 * q + 1], C1b);
        }
        E.q2 = tanh_pre(upadd(add2(C2a, C2b))) * w32;
        qslot[lane] = E.q2;
        E.q3 = tanh_pre(upadd(add2(C3a, C3b))) * w32;
        E.q1 = tanh_pre(upadd(add2(C1a, C1b))) * w32;
    };

    auto phaseC = [&](Elem& E, const float* qslot) {
        const ulonglong2* qv = reinterpret_cast<const ulonglong2*>(qslot);
        ulonglong2 a0 = qv[0], a1 = qv[1], a2 = qv[2], a3 = qv[3],
                   a4 = qv[4], a5 = qv[5], a6 = qv[6], a7 = qv[7];
        ull s0 = add2(add2(a0.x, a0.y), add2(a1.x, a1.y));
        ull s1 = add2(add2(a2.x, a2.y), add2(a3.x, a3.y));
        ull s2 = add2(add2(a4.x, a4.y), add2(a5.x, a5.y));
        ull s3 = add2(add2(a6.x, a6.y), add2(a7.x, a7.y));
        E.r3s23 = upadd(add2(add2(s0, s1), add2(s2, s3))) + b32;
        E.r3s4  = bfly(E.q3) + b32;
        E.r3s1n = bfly(E.q1) + b32;
    };

    auto phaseD = [&](Elem& E, int p) {
        float k10, k11; kof(E.x0, E.x1, E.r3s1, E.cafs, k10, k11);
        float xb0 = fmaf(0.5f, k10, E.x0), xb1 = fmaf(0.5f, k11, E.x1);
        float k20, k21; kof(xb0, xb1, E.r3s23, E.cafs, k20, k21);
        float xc0 = fmaf(0.5f, k20, E.x0), xc1 = fmaf(0.5f, k21, E.x1);
        float k30, k31; kof(xc0, xc1, E.r3s23, E.cafs, k30, k31);
        float xd0 = E.x0 + k30, xd1 = E.x1 + k31;
        float k40, k41; kof(xd0, xd1, E.r3s4, E.cafs, k40, k41);
        float nx0 = fmaf(k10 + 2.0f * (k20 + k30) + k40, 1.0f / 6.0f, E.x0);
        float nx1 = fmaf(k11 + 2.0f * (k21 + k31) + k41, 1.0f / 6.0f, E.x1);
        E.xq[p & 7] = E.px;
        E.up[p & 7] = E.u;
        ull S4n = 0ull;
#pragma unroll
        for (int j = 0; j < 7; ++j)
            S4n = fma2(E.xq[(p + 2 + j) & 7], w30p[j], S4n);
        E.S4p  = S4n;
        E.S1s  = E.S4s;
        E.Uc   = E.Un;
        E.r3s1 = E.r3s1n;
        E.x0 = nx0; E.x1 = nx1;
    };

    // ---- pipeline bootstrap (both elements; uses parity-1 buffers) ----------
    auto boot = [&](Elem& E, float* buf) {
        ull S1 = 0ull;
#pragma unroll
        for (int j = 0; j < 8; ++j) S1 = fma2(E.xq[j], w30p[j], S1);
        float Ua = b30s, Ub = 0.0f;
#pragma unroll
        for (int k = 0; k < 8; k += 2) {
            Ua = fmaf(E.up[k],     wu[k],     Ua);
            Ub = fmaf(E.up[k + 1], wu[k + 1], Ub);
        }
        E.S1s = upadd(S1);
        E.Uc  = Ua + Ub;
        buf[lane] = tanh_pre(E.S1s + E.Uc);
    };
    boot(A, bufA0 + 96);
    boot(B, bufB0 + 96);
    __syncwarp();
    {
        auto mv1 = [&](const float* buf) -> float {
            ull C = b31p;
            const ulonglong2* bq = reinterpret_cast<const ulonglong2*>(buf);
#pragma unroll
            for (int q = 0; q < 8; ++q) {
                ulonglong2 v = bq[q];
                C = fma2(v.x, w31p[2 * q],     C);
                C = fma2(v.y, w31p[2 * q + 1], C);
            }
            return bfly(tanh_pre(upadd(C)) * w32) + b32;
        };
        A.r3s1 = mv1(bufA0 + 96);
        B.r3s1 = mv1(bufB0 + 96);
    }
    __syncwarp();
    {
        ull S4pA = 0ull, S4pB = 0ull;
#pragma unroll
        for (int j = 0; j < 7; ++j) {
            S4pA = fma2(A.xq[(1 + j) & 7], w30p[j], S4pA);
            S4pB = fma2(B.xq[(1 + j) & 7], w30p[j], S4pB);
        }
        A.S4p = S4pA; B.S4p = S4pB;
    }

    // ---- main loop ------------------------------------------------------------
#pragma unroll 1
    for (int tb = 0; tb < kT; tb += 8) {
        float4 ua0 = __ldg(uptrA + (tb >> 2));
        float4 ua1 = __ldg(uptrA + (tb >> 2) + 1);
        float4 ub0 = __ldg(uptrB + (tb >> 2));
        float4 ub1 = __ldg(uptrB + (tb >> 2) + 1);
        float uA[8] = {ua0.x, ua0.y, ua0.z, ua0.w, ua1.x, ua1.y, ua1.z, ua1.w};
        float uB[8] = {ub0.x, ub0.y, ub0.z, ub0.w, ub1.x, ub1.y, ub1.z, ub1.w};

#pragma unroll
        for (int p = 0; p < 8; ++p) {
            if (lane == 0) {
                outA[tb + p] = make_float2(A.x0, A.x1);
                outB[tb + p] = make_float2(B.x0, B.x1);
            }
            float* bA = bufA0 + (p & 1) * 96;
            float* bB = bufB0 + (p & 1) * 96;
            phaseA(A, p, uA[p], bA);
            phaseA(B, p, uB[p], bB);
            __syncwarp();
            phaseB(A, bA, qbufA);
            phaseB(B, bB, qbufB);
            __syncwarp();
            phaseC(A, qbufA);
            phaseC(B, qbufB);
            phaseD(A, p);
            phaseD(B, p);
        }
    }
}

}  // namespace

extern "C" void kernel_launch(void* const* d_in, const int* in_sizes, int n_in,
                              void* d_out, int out_size) {
    (void)in_sizes; (void)n_in; (void)out_size;
    const float* useq = (const float*)d_in[0];
    const float* xz0  = (const float*)d_in[1];
    const float* r1W0 = (const float*)d_in[2];
    const float* r1b0 = (const float*)d_in[3];
    const float* r1W1 = (const float*)d_in[4];
    const float* r1b1 = (const float*)d_in[5];
    const float* r1W2 = (const float*)d_in[6];
    const float* r1b2 = (const float*)d_in[7];
    const float* r2W0 = (const float*)d_in[8];
    const float* r2b0 = (const float*)d_in[9];
    const float* r2W1 = (const float*)d_in[10];
    const float* r2b1 = (const float*)d_in[11];
    const float* r2W2 = (const float*)d_in[12];
    const float* r2b2 = (const float*)d_in[13];
    const float* r3W0 = (const float*)d_in[14];
    const float* r3b0 = (const float*)d_in[15];
    const float* r3W1 = (const float*)d_in[16];
    const float* r3b1 = (const float*)d_in[17];
    const float* r3W2 = (const float*)d_in[18];
    const float* r3b2 = (const float*)d_in[19];
    float* out = (float*)d_out;

    build_all<<<(2 * kN + 127) / 128, 128>>>(
        r1W0, r1b0, r1W1, r1b1, r1W2, r1b2,
        r2W0, r2b0, r2W1, r2b1, r2W2, r2b2);
    rk4_kernel<<<kB / 8, 128>>>(useq, xz0,
                                r3W0, r3b0, r3W1, r3b1, r3W2, r3b2,
                                out);
}

// round 8
// speedup vs baseline: 1.4940x; 1.4940x over previous
#include <cuda_runtime.h>
#include <math.h>

// ReacPartialGbModel: B=4096 RK4 integrations, T=256 steps.
// r1(x0), r2(x1) -> cubic-Hermite LUTs (ODE affine terms folded), now built at
// h=1/32 over [-16,16) and COPIED INTO SHARED MEMORY per block: the RK chain's
// serial lookups become fixed-latency broadcast LDS (no l1tex LDG queueing).
// r3 software-pipelined (k1-stage r3 of step t+1 computed during step t).
// One warp per batch element; lane = hidden unit.

namespace {

constexpr int kT = 256;
constexpr int kB = 4096;
constexpr int kN2    = 1024;            // smem LUT intervals
constexpr float kLo2   = -16.0f;
constexpr float kH2    = 1.0f / 32.0f;
constexpr float kInvH2 = 32.0f;
constexpr float kSc   = 2.885390081777927f;  // 2*log2(e)

// global staging for the LUTs (built once per launch, copied to smem per block)
__device__ __align__(16) float4 g_lutX2[2 * kN2];   // [2i]=A, [2i+1]=R
__device__ __align__(16) float4 g_lutY2[kN2];       // B

typedef unsigned long long ull;

// ---------------- helpers ---------------------------------------------------
__device__ __forceinline__ float tanh_acc(float x) {   // build-time, ~1e-7
    float ax = fabsf(x);
    float e  = __expf(-2.0f * ax);
    float r  = __fdividef(1.0f - e, 1.0f + e);
    return copysignf(r, x);
}
__device__ __forceinline__ float tanh_pre(float a) {   // input prescaled 2*log2e
    float e; asm("ex2.approx.f32 %0, %1;" : "=f"(e) : "f"(a));
    float s = e + 1.0f;
    float r; asm("rcp.approx.f32 %0, %1;" : "=f"(r) : "f"(s));
    return fmaf(-2.0f, r, 1.0f);
}
__device__ __forceinline__ ull fma2(ull a, ull b, ull c) {
    ull d; asm("fma.rn.f32x2 %0, %1, %2, %3;" : "=l"(d) : "l"(a), "l"(b), "l"(c));
    return d;
}
__device__ __forceinline__ ull add2(ull a, ull b) {
    ull d; asm("add.rn.f32x2 %0, %1, %2;" : "=l"(d) : "l"(a), "l"(b));
    return d;
}
__device__ __forceinline__ ull pk(float lo, float hi) {
    ull d; asm("mov.b64 %0, {%1, %2};" : "=l"(d) : "f"(lo), "f"(hi));
    return d;
}
__device__ __forceinline__ float upadd(ull v) {
    float lo, hi; asm("mov.b64 {%0, %1}, %2;" : "=f"(lo), "=f"(hi) : "l"(v));
    return lo + hi;
}
__device__ __forceinline__ float bfly(float v) {
#pragma unroll
    for (int m = 16; m > 0; m >>= 1) v += __shfl_xor_sync(0xffffffffu, v, m);
    return v;
}

// ---------------- merged build kernel ---------------------------------------
__device__ void eval_raw(float x,
                         const float* __restrict__ w0, const float* __restrict__ b0,
                         const float* __restrict__ w1, const float* __restrict__ b1,
                         const float* __restrict__ w2, const float* __restrict__ b2,
                         float& y_out, float& d_out)
{
    float t0[32], s0[32];
#pragma unroll
    for (int i = 0; i < 32; ++i) {
        float a  = fmaf(w0[i], x, b0[i]);
        float th = tanh_acc(a);
        t0[i] = th;
        s0[i] = (1.0f - th * th) * w0[i];
    }
    float y = b2[0], d = 0.0f;
    for (int j = 0; j < 32; ++j) {
        float a = b1[j], da = 0.0f;
#pragma unroll
        for (int i = 0; i < 32; ++i) {
            float w = w1[i * 32 + j];
            a  = fmaf(t0[i], w, a);
            da = fmaf(s0[i], w, da);
        }
        float th = tanh_acc(a);
        y = fmaf(w2[j], th, y);
        d = fmaf(w2[j] * (1.0f - th * th), da, d);
    }
    y_out = y; d_out = d;
}

__device__ __forceinline__ float4 hermite2(float y0, float d0, float y1, float d1) {
    float hd0 = kH2 * d0, hd1 = kH2 * d1;
    float dy  = y1 - y0;
    return make_float4(y0, hd0,
                       3.0f * dy - 2.0f * hd0 - hd1,
                       -2.0f * dy + hd0 + hd1);
}

__global__ void build_all(const float* __restrict__ W0, const float* __restrict__ B0,
                          const float* __restrict__ W1, const float* __restrict__ B1,
                          const float* __restrict__ W2, const float* __restrict__ B2,
                          const float* __restrict__ V0, const float* __restrict__ C0,
                          const float* __restrict__ V1, const float* __restrict__ C1,
                          const float* __restrict__ V2, const float* __restrict__ C2)
{
    int idx = blockIdx.x * blockDim.x + threadIdx.x;
    if (idx >= 2 * kN2) return;
    int net = idx / kN2;
    int i   = idx - net * kN2;
    float xa = kLo2 + i * kH2;
    float xb = xa + kH2;
    float y0, d0, y1, d1;
    if (net == 0) {
        eval_raw(xa, W0, B0, W1, B1, W2, B2, y0, d0);
        eval_raw(xb, W0, B0, W1, B1, W2, B2, y1, d1);
        // r1 = 0.3*y.  A = (0.1*Ca + r1)/0.3, Ca = 0.3x+0.5 ; R = r1*5
        float A0 = (0.1f * fmaf(0.3f, xa, 0.5f) + 0.3f * y0) * (1.0f / 0.3f);
        float A1 = (0.1f * fmaf(0.3f, xb, 0.5f) + 0.3f * y1) * (1.0f / 0.3f);
        float Ad0 = (0.03f + 0.3f * d0) * (1.0f / 0.3f);
        float Ad1 = (0.03f + 0.3f * d1) * (1.0f / 0.3f);
        g_lutX2[2 * i]     = hermite2(A0, Ad0, A1, Ad1);
        g_lutX2[2 * i + 1] = hermite2(1.5f * y0, 1.5f * d0, 1.5f * y1, 1.5f * d1);
    } else {
        eval_raw(xa, V0, C0, V1, C1, V2, C2, y0, d0);
        eval_raw(xb, V0, C0, V1, C1, V2, C2, y1, d1);
        // r2 = 0.2*y.  B = (0.1*Cb + 3*r2)*5, Cb = 0.2x+0.5
        float Bv0 = (0.1f * fmaf(0.2f, xa, 0.5f) + 0.6f * y0) * 5.0f;
        float Bv1 = (0.1f * fmaf(0.2f, xb, 0.5f) + 0.6f * y1) * 5.0f;
        float Bd0 = (0.02f + 0.6f * d0) * 5.0f;
        float Bd1 = (0.02f + 0.6f * d1) * 5.0f;
        g_lutY2[i] = hermite2(Bv0, Bd0, Bv1, Bd1);
    }
}

// ---------------- main kernel ------------------------------------------------
// dynamic smem layout (floats): [4 x 224 warp bufs][LUTX 2048 float4][LUTY 1024 float4]
constexpr int kSbufFloats = 4 * 224;                  // 896 floats = 3584 B (16B aligned)
constexpr int kSmemBytes  = kSbufFloats * 4 + 2 * kN2 * 16 + kN2 * 16;  // 52736

__global__ void __launch_bounds__(128, 4)
rk4_kernel(const float* __restrict__ useq, const float* __restrict__ xz0,
           const float* __restrict__ r3W0, const float* __restrict__ r3b0,
           const float* __restrict__ r3W1, const float* __restrict__ r3b1,
           const float* __restrict__ r3W2, const float* __restrict__ r3b2,
           float* __restrict__ out)
{
    extern __shared__ __align__(16) float smemraw[];
    const int wslot = threadIdx.x >> 5;
    const int wid   = blockIdx.x * 4 + wslot;
    const int lane  = threadIdx.x & 31;

    float*  swarp = smemraw + wslot * 224;            // per-warp scratch
    float4* sX    = reinterpret_cast<float4*>(smemraw + kSbufFloats);
    float4* sY    = sX + 2 * kN2;

    // ---- copy LUTs into shared memory --------------------------------------
    for (int k = threadIdx.x; k < 2 * kN2; k += 128) sX[k] = __ldg(&g_lutX2[k]);
    for (int k = threadIdx.x; k < kN2;     k += 128) sY[k] = __ldg(&g_lutY2[k]);
    __syncthreads();

    // ---- p3 weights, prescaled by 2*log2e, packed pairs --------------------
    ull w30p[8], w31p[16];
    float wu[8];
#pragma unroll
    for (int j = 0; j < 8; ++j)
        w30p[j] = pk(r3W0[(2 * j) * 32 + lane] * kSc,
                     r3W0[(2 * j + 1) * 32 + lane] * kSc);
#pragma unroll
    for (int k = 0; k < 8; ++k) wu[k] = r3W0[(16 + k) * 32 + lane] * kSc;
#pragma unroll
    for (int j = 0; j < 16; ++j)
        w31p[j] = pk(r3W1[(2 * j) * 32 + lane] * kSc,
                     r3W1[(2 * j + 1) * 32 + lane] * kSc);
    const float b30s = r3b0[lane] * kSc;
    const ull   b31p = pk(r3b1[lane] * kSc, 0.0f);
    const float w32  = r3W2[lane], b32 = r3b2[0];

    // ---- state: x scalar, history as packed register ring ------------------
    const float* xz = xz0 + wid * 26;
    float x0 = xz[0], x1 = xz[1];
    ull xq[8];
    float up[8];
#pragma unroll
    for (int j = 0; j < 8; ++j) xq[j] = pk(xz[2 + 2 * j], xz[3 + 2 * j]);
#pragma unroll
    for (int k = 0; k < 8; ++k) up[k] = xz[18 + k];

    const float4* uptr4 = reinterpret_cast<const float4*>(useq + wid * kT);
    float2* outp = reinterpret_cast<float2*>(out) + wid * kT;

    auto kof = [&](float xa0, float xa1, float r3s, float cafs,
                   float& k0, float& k1v) {
        float xf0 = fmaf(xa0, kInvH2, (float)(kN2 / 2));
        float f0  = fminf(fmaxf(floorf(xf0), 0.0f), (float)(kN2 - 1));
        float t0  = xf0 - f0;
        int   i0  = (int)f0;
        float4 cA = sX[2 * i0];
        float4 cR = sX[2 * i0 + 1];
        float xf1 = fmaf(xa1, kInvH2, (float)(kN2 / 2));
        float f1  = fminf(fmaxf(floorf(xf1), 0.0f), (float)(kN2 - 1));
        float t1  = xf1 - f1;
        int   i1  = (int)f1;
        float4 cB = sY[i1];
        float Av  = fmaf(fmaf(fmaf(cA.w, t0, cA.z), t0, cA.y), t0, cA.x);
        float Rv  = fmaf(fmaf(fmaf(cR.w, t0, cR.z), t0, cR.y), t0, cR.x);
        float Bv  = fmaf(fmaf(fmaf(cB.w, t1, cB.z), t1, cB.y), t1, cB.x);
        k0  = cafs - Av;
        k1v = Rv - Bv + r3s;
    };

    // ---- pipeline bootstrap (step 0, ring phase p=0) ------------------------
    float S1s, Uc, r3s1;
    {
        ull S1 = 0ull;
#pragma unroll
        for (int j = 0; j < 8; ++j) S1 = fma2(xq[j], w30p[j], S1);
        float Ua = b30s, Ub = 0.0f;
#pragma unroll
        for (int k = 0; k < 8; k += 2) {
            Ua = fmaf(up[k],     wu[k],     Ua);
            Ub = fmaf(up[k + 1], wu[k + 1], Ub);
        }
        S1s = upadd(S1);
        Uc  = Ua + Ub;
        float h = tanh_pre(S1s + Uc);
        swarp[lane] = h;
        __syncwarp();
        ull C = b31p;
        const ulonglong2* bq = reinterpret_cast<const ulonglong2*>(swarp);
#pragma unroll
        for (int q = 0; q < 8; ++q) {
            ulonglong2 v = bq[q];
            C = fma2(v.x, w31p[2 * q],     C);
            C = fma2(v.y, w31p[2 * q + 1], C);
        }
        __syncwarp();
        r3s1 = bfly(tanh_pre(upadd(C)) * w32) + b32;
    }
    ull S4p = 0ull;
#pragma unroll
    for (int j = 0; j < 7; ++j) S4p = fma2(xq[(1 + j) & 7], w30p[j], S4p);

#pragma unroll 1
    for (int tb = 0; tb < kT; tb += 8) {
        float4 ua = __ldg(uptr4 + (tb >> 2));
        float4 ub = __ldg(uptr4 + (tb >> 2) + 1);
        float uu[8] = {ua.x, ua.y, ua.z, ua.w, ub.x, ub.y, ub.z, ub.w};

#pragma unroll
        for (int p = 0; p < 8; ++p) {
            const float u = uu[p];
            if (lane == 0) outp[tb + p] = make_float2(x0, x1);
            const float cafs = fmaf(u, 0.5f / 3.0f, 1.0f / 3.0f);

            // ---- fast a3 computation (short path after x arrives) ----------
            ull px = pk(x0, x1);
            float S4s = upadd(fma2(px, w30p[7], S4p));
            float a3_23 = fmaf(0.5f, S1s + S4s, Uc);
            float a3_4  = S4s + Uc;
            float Una = b30s, Unb = 0.0f;
#pragma unroll
            for (int k = 0; k < 6; k += 2) {
                Una = fmaf(up[(p + 1 + k) & 7], wu[k],     Una);
                Unb = fmaf(up[(p + 2 + k) & 7], wu[k + 1], Unb);
            }
            Una = fmaf(up[(p + 7) & 7], wu[6], Una);
            Unb = fmaf(u, wu[7], Unb);
            float Un = Una + Unb;
            float a3_1n = S4s + Un;        // k1-stage preact for step t+1

            // ---- three p3 evals in one broadcast round ----------------------
            float h2  = tanh_pre(a3_23);
            float h3  = tanh_pre(a3_4);
            float h1n = tanh_pre(a3_1n);
            float* buf = swarp + (p & 1) * 96;
            buf[lane]      = h2;
            buf[32 + lane] = h3;
            buf[64 + lane] = h1n;
            __syncwarp();
            ull C2a = b31p, C2b = 0ull, C3a = b31p, C3b = 0ull,
                C1a = b31p, C1b = 0ull;
            const ulonglong2* bq = reinterpret_cast<const ulonglong2*>(buf);
#pragma unroll
            for (int q = 0; q < 8; ++q) {
                ulonglong2 v2 = bq[q];
                C2a = fma2(v2.x, w31p[2 * q],     C2a);
                C2b = fma2(v2.y, w31p[2 * q + 1], C2b);
                ulonglong2 v3 = bq[8 + q];
                C3a = fma2(v3.x, w31p[2 * q],     C3a);
                C3b = fma2(v3.y, w31p[2 * q + 1], C3b);
                ulonglong2 v1 = bq[16 + q];
                C1a = fma2(v1.x, w31p[2 * q],     C1a);
                C1b = fma2(v1.y, w31p[2 * q + 1], C1b);
            }
            // q2 critical -> smem tree; q3, q1n off-path -> butterflies
            float q2 = tanh_pre(upadd(add2(C2a, C2b))) * w32;
            float* qbuf = swarp + 192;
            qbuf[lane] = q2;
            float q3 = tanh_pre(upadd(add2(C3a, C3b))) * w32;
            float q1 = tanh_pre(upadd(add2(C1a, C1b))) * w32;
            __syncwarp();
            ull s0, s1, s2, s3;
            {
                const ulonglong2* qv = reinterpret_cast<const ulonglong2*>(qbuf);
                ulonglong2 a0 = qv[0], a1 = qv[1], a2 = qv[2], a3 = qv[3],
                           a4 = qv[4], a5 = qv[5], a6 = qv[6], a7 = qv[7];
                s0 = add2(add2(a0.x, a0.y), add2(a1.x, a1.y));
                s1 = add2(add2(a2.x, a2.y), add2(a3.x, a3.y));
                s2 = add2(add2(a4.x, a4.y), add2(a5.x, a5.y));
                s3 = add2(add2(a6.x, a6.y), add2(a7.x, a7.y));
            }
            float r3s23 = upadd(add2(add2(s0, s1), add2(s2, s3))) + b32;
            float r3s4  = bfly(q3) + b32;
            float r3s1n = bfly(q1) + b32;

            // ---- RK4 k-chain: stage 1 uses carried r3s1 (starts early) -----
            float k10, k11; kof(x0, x1, r3s1, cafs, k10, k11);
            float xb0 = fmaf(0.5f, k10, x0), xb1 = fmaf(0.5f, k11, x1);
            float k20, k21; kof(xb0, xb1, r3s23, cafs, k20, k21);
            float xc0 = fmaf(0.5f, k20, x0), xc1 = fmaf(0.5f, k21, x1);
            float k30, k31; kof(xc0, xc1, r3s23, cafs, k30, k31);
            float xd0 = x0 + k30, xd1 = x1 + k31;
            float k40, k41; kof(xd0, xd1, r3s4, cafs, k40, k41);

            float nx0 = fmaf(k10 + 2.0f * (k20 + k30) + k40, 1.0f / 6.0f, x0);
            float nx1 = fmaf(k11 + 2.0f * (k21 + k31) + k41, 1.0f / 6.0f, x1);

            // ---- ring + pipeline updates (off critical path) ----------------
            xq[p & 7] = px;
            up[p & 7] = u;
            ull S4n = 0ull;
#pragma unroll
            for (int j = 0; j < 7; ++j)
                S4n = fma2(xq[(p + 2 + j) & 7], w30p[j], S4n);
            S4p = S4n;
            S1s = S4s;
            Uc  = Un;
            r3s1 = r3s1n;
            x0 = nx0; x1 = nx1;
        }
    }
}

}  // namespace

extern "C" void kernel_launch(void* const* d_in, const int* in_sizes, int n_in,
                              void* d_out, int out_size) {
    (void)in_sizes; (void)n_in; (void)out_size;
    const float* useq = (const float*)d_in[0];
    const float* xz0  = (const float*)d_in[1];
    const float* r1W0 = (const float*)d_in[2];
    const float* r1b0 = (const float*)d_in[3];
    const float* r1W1 = (const float*)d_in[4];
    const float* r1b1 = (const float*)d_in[5];
    const float* r1W2 = (const float*)d_in[6];
    const float* r1b2 = (const float*)d_in[7];
    const float* r2W0 = (const float*)d_in[8];
    const float* r2b0 = (const float*)d_in[9];
    const float* r2W1 = (const float*)d_in[10];
    const float* r2b1 = (const float*)d_in[11];
    const float* r2W2 = (const float*)d_in[12];
    const float* r2b2 = (const float*)d_in[13];
    const float* r3W0 = (const float*)d_in[14];
    const float* r3b0 = (const float*)d_in[15];
    const float* r3W1 = (const float*)d_in[16];
    const float* r3b1 = (const float*)d_in[17];
    const float* r3W2 = (const float*)d_in[18];
    const float* r3b2 = (const float*)d_in[19];
    float* out = (float*)d_out;

    static_assert(kSmemBytes <= 64 * 1024, "smem");
    cudaFuncSetAttribute(rk4_kernel, cudaFuncAttributeMaxDynamicSharedMemorySize,
                         kSmemBytes);

    build_all<<<(2 * kN2 + 127) / 128, 128>>>(
        r1W0, r1b0, r1W1, r1b1, r1W2, r1b2,
        r2W0, r2b0, r2W1, r2b1, r2W2, r2b2);
    rk4_kernel<<<kB / 4, 128, kSmemBytes>>>(useq, xz0,
                                            r3W0, r3b0, r3W1, r3b1, r3W2, r3b2,
                                            out);
}